// round 16
// baseline (speedup 1.0000x reference)
#include <cuda_runtime.h>
#include <cuda_bf16.h>
#include <cstdint>

// ---------------- problem constants ----------------
#define NB      32
#define NNODE   4096
#define NEDGE   16384
#define F1      16
#define F2      128
#define F3      256
#define KHEAD   (NNODE * F3)   // 1,048,576
#define NROWS   (NB * NNODE)   // 131072

// ---------------- scratch ----------------
__device__ float g_h1[(size_t)NB * NNODE * F2];
__device__ float g_a2[(size_t)NB * NNODE * F2];
__device__ float g_h2[(size_t)NB * NNODE * F3];
__device__ float g_deg[NNODE];
__device__ float g_dinv[NNODE];
__device__ int   g_cnt[NNODE];
__device__ int   g_fill[NNODE];
__device__ int   g_rowptr[NNODE + 1];
__device__ int   g_col[NEDGE];
__device__ float g_nrm[NEDGE];
__device__ float g_P[NB * 80];
__device__ int   g_is64;

#define HGB 512
__device__ float g_Ppart[HGB][NB * 80];   // 5.24 MB per-block head partials

// ---------------- helpers ----------------
// truncation-based split of a float pair into bf16x2 hi/lo words.
__device__ __forceinline__ void split2(float x, float y, uint32_t& hi, uint32_t& lo) {
    uint32_t xb = __float_as_uint(x), yb = __float_as_uint(y);
    hi = __byte_perm(xb, yb, 0x7632);
    float lx = x - __uint_as_float(xb & 0xffff0000u);
    float ly = y - __uint_as_float(yb & 0xffff0000u);
    lo = __byte_perm(__float_as_uint(lx), __float_as_uint(ly), 0x7632);
}
// D += A(16x16 bf16) * B(16x8 bf16), f32 accum. m16n8k16 fragments.
__device__ __forceinline__ void mma_bf16(float* d, const uint32_t* a, uint32_t b0, uint32_t b1) {
    asm volatile(
        "mma.sync.aligned.m16n8k16.row.col.f32.bf16.bf16.f32 "
        "{%0,%1,%2,%3}, {%4,%5,%6,%7}, {%8,%9}, {%0,%1,%2,%3};"
        : "+f"(d[0]), "+f"(d[1]), "+f"(d[2]), "+f"(d[3])
        : "r"(a[0]), "r"(a[1]), "r"(a[2]), "r"(a[3]), "r"(b0), "r"(b1));
}
// head weight fragment load: rows r0, r0+1, r0+8, r0+9 at output-col ncol of [v1W|advW|0]
__device__ __forceinline__ void load_w4(float* dst, const float* __restrict__ v1W,
                                        const float* __restrict__ advW, int r0, int ncol) {
    if (ncol < 64) {
        const float* p = v1W + (size_t)r0 * 64 + ncol;
        dst[0] = p[0]; dst[1] = p[64]; dst[2] = p[512]; dst[3] = p[576];
    } else if (ncol < 76) {
        const float* p = advW + (size_t)r0 * 12 + (ncol - 64);
        dst[0] = p[0]; dst[1] = p[12]; dst[2] = p[96]; dst[3] = p[108];
    } else {
        dst[0] = dst[1] = dst[2] = dst[3] = 0.f;
    }
}

// ---------------- edge read helper ----------------
__device__ __forceinline__ void read_edge(const void* ei, int e, int& src, int& dst) {
    if (g_is64) {
        const long long* p = (const long long*)ei;
        src = (int)p[e]; dst = (int)p[NEDGE + e];
    } else {
        const int* p = (const int*)ei;
        src = p[e]; dst = p[NEDGE + e];
    }
}

// ---------------- K0 ----------------
__global__ void zero_kernel(const int* __restrict__ ei32) {
    int i = blockIdx.x * blockDim.x + threadIdx.x;
    if (i < NNODE) { g_deg[i] = 0.f; g_cnt[i] = 0; g_fill[i] = 0; }
    if (i == 0) {
        int any = 0;
        for (int k = 0; k < 256; k++) any |= ei32[2 * k + 1];
        g_is64 = (any == 0) ? 1 : 0;
    }
}

// ---------------- K1 ----------------
__global__ void degcnt_kernel(const void* __restrict__ ei, const float* __restrict__ ew) {
    int e = blockIdx.x * blockDim.x + threadIdx.x;
    if (e >= NEDGE) return;
    int src, dst;
    read_edge(ei, e, src, dst);
    atomicAdd(&g_deg[dst], ew[e]);
    atomicAdd(&g_cnt[dst], 1);
}

// ---------------- K2 ----------------
__global__ __launch_bounds__(1024) void scan_kernel() {
    __shared__ int ss[1024];
    int t = threadIdx.x;
    int loc[4]; int s = 0;
#pragma unroll
    for (int i = 0; i < 4; i++) { loc[i] = s; s += g_cnt[4 * t + i]; }
    ss[t] = s;
    __syncthreads();
    int mysum = s;
    for (int off = 1; off < 1024; off <<= 1) {
        int v = (t >= off) ? ss[t - off] : 0;
        __syncthreads();
        ss[t] += v;
        __syncthreads();
    }
    int excl = ss[t] - mysum;
#pragma unroll
    for (int i = 0; i < 4; i++) {
        g_rowptr[4 * t + i] = excl + loc[i];
        g_dinv[4 * t + i] = rsqrtf(g_deg[4 * t + i] + 1.0f);
    }
    if (t == 1023) g_rowptr[NNODE] = ss[t];
}

// ---------------- K3 ----------------
__global__ void fill_kernel(const void* __restrict__ ei, const float* __restrict__ ew) {
    int e = blockIdx.x * blockDim.x + threadIdx.x;
    if (e >= NEDGE) return;
    int src, dst;
    read_edge(ei, e, src, dst);
    int pos = g_rowptr[dst] + atomicAdd(&g_fill[dst], 1);
    g_col[pos] = src;
    g_nrm[pos] = ew[e] * g_dinv[src] * g_dinv[dst];
}

// ---------------- K4: FUSED aggregate x (F=16) + gemm1 -> h1 ----------------
// block = node, 512 thr = 32 b x 16 f. Stage 1: a1[b][f] in smem (same gather
// as before). Stage 2: thread (b,f) computes h1 row (b*NNODE+n), cols f*8..f*8+7.
__global__ __launch_bounds__(512) void agg16_gemm1_kernel(const float* __restrict__ x,
                                                          const float* __restrict__ W1,
                                                          const float* __restrict__ b1) {
    __shared__ float sA[32][17];
    __shared__ float sW[16][128];
    __shared__ float sb[128];
    int n = blockIdx.x;
    int tid = threadIdx.x;
    int b = tid >> 4, f = tid & 15;

    for (int id = tid; id < 16 * 128; id += 512) sW[id >> 7][id & 127] = W1[id];
    if (tid < 128) sb[tid] = b1[tid];

    int beg = g_rowptr[n], end = g_rowptr[n + 1];
    float d = g_dinv[n];
    float d2 = d * d;
    const float* xb = x + (size_t)b * (NNODE * F1);
    float acc = d2 * xb[n * F1 + f];
    for (int j = beg; j < end; j++)
        acc = fmaf(g_nrm[j], xb[(size_t)g_col[j] * F1 + f], acc);
    sA[b][f] = acc;
    __syncthreads();

    float o[8];
#pragma unroll
    for (int j = 0; j < 8; j++) o[j] = sb[f * 8 + j];
#pragma unroll
    for (int k = 0; k < 16; k++) {
        float a = sA[b][k];
        float4 w0 = *(const float4*)&sW[k][f * 8];
        float4 w1 = *(const float4*)&sW[k][f * 8 + 4];
        o[0] = fmaf(a, w0.x, o[0]); o[1] = fmaf(a, w0.y, o[1]);
        o[2] = fmaf(a, w0.z, o[2]); o[3] = fmaf(a, w0.w, o[3]);
        o[4] = fmaf(a, w1.x, o[4]); o[5] = fmaf(a, w1.y, o[5]);
        o[6] = fmaf(a, w1.z, o[6]); o[7] = fmaf(a, w1.w, o[7]);
    }
    float* dst = g_h1 + ((size_t)b * NNODE + n) * F2 + f * 8;
#pragma unroll
    for (int j = 0; j < 8; j++) o[j] = fmaxf(o[j], 0.f);
    *(float4*)(dst)     = make_float4(o[0], o[1], o[2], o[3]);
    *(float4*)(dst + 4) = make_float4(o[4], o[5], o[6], o[7]);
}

// ---------------- K6: aggregate h1 (F=128) ----------------
__global__ __launch_bounds__(512) void agg128_kernel() {
    int n = blockIdx.x;
    int tid = threadIdx.x;
    int b = tid >> 4, q = tid & 15;
    int beg = g_rowptr[n], end = g_rowptr[n + 1];
    float d = g_dinv[n];
    float d2 = d * d;
    const float4* hb = (const float4*)g_h1 + (size_t)b * (NNODE * 32);
    float4 s0 = hb[(size_t)n * 32 + q];
    float4 s1 = hb[(size_t)n * 32 + 16 + q];
    float4 a0 = make_float4(d2 * s0.x, d2 * s0.y, d2 * s0.z, d2 * s0.w);
    float4 a1 = make_float4(d2 * s1.x, d2 * s1.y, d2 * s1.z, d2 * s1.w);
    for (int j = beg; j < end; j++) {
        float w = g_nrm[j];
        size_t c = (size_t)g_col[j] * 32;
        float4 v0 = hb[c + q];
        float4 v1 = hb[c + 16 + q];
        a0.x = fmaf(w, v0.x, a0.x); a0.y = fmaf(w, v0.y, a0.y);
        a0.z = fmaf(w, v0.z, a0.z); a0.w = fmaf(w, v0.w, a0.w);
        a1.x = fmaf(w, v1.x, a1.x); a1.y = fmaf(w, v1.y, a1.y);
        a1.z = fmaf(w, v1.z, a1.z); a1.w = fmaf(w, v1.w, a1.w);
    }
    float4* ob = (float4*)g_a2 + (size_t)b * (NNODE * 32);
    ob[(size_t)n * 32 + q] = a0;
    ob[(size_t)n * 32 + 16 + q] = a1;
}

// ---------------- K7: gemm2, bf16 split mma, double-buffered smem ----------------
#define G2_BUFU 10240    // u32 per buffer
#define G2_SMEM 81920

__global__ __launch_bounds__(256, 2) void gemm2_mma_kernel(const float* __restrict__ W2,
                                                           const float* __restrict__ b2) {
    extern __shared__ uint32_t smu[];

    int tid = threadIdx.x;
    int wid = tid >> 5, lane = tid & 31;
    int gid = lane >> 2, tig = lane & 3;
    int wm = wid & 1, wn = wid >> 1;
    int m0 = blockIdx.y * 128;
    int n0 = blockIdx.x * 128;

    float acc[4][4][4];
#pragma unroll
    for (int i = 0; i < 4; i++)
#pragma unroll
        for (int j = 0; j < 4; j++)
#pragma unroll
            for (int r = 0; r < 4; r++) acc[i][j][r] = 0.f;

    float2 rA[8];
    float  rBx[8], rBy[8];
    // prefetch chunk 0
#pragma unroll
    for (int i = 0; i < 8; i++) {
        int idx = tid + i * 256;
        int m = idx >> 4, kp = idx & 15;
        rA[i] = *(const float2*)(g_a2 + (size_t)(m0 + m) * F2 + 2 * kp);
    }
#pragma unroll
    for (int i = 0; i < 8; i++) {
        int idx = tid + i * 256;
        int kp = idx >> 7, n = idx & 127;
        rBx[i] = W2[(size_t)(2 * kp) * F3 + n0 + n];
        rBy[i] = W2[(size_t)(2 * kp + 1) * F3 + n0 + n];
    }
    // stage chunk 0 into buffer 0
    {
        uint32_t* uAh = smu;
        uint32_t* uAl = smu + 2560;
        uint32_t* uBh = smu + 5120;
        uint32_t* uBl = smu + 7680;
#pragma unroll
        for (int i = 0; i < 8; i++) {
            int idx = tid + i * 256;
            int m = idx >> 4, kp = idx & 15;
            uint32_t hi, lo;
            split2(rA[i].x, rA[i].y, hi, lo);
            uAh[m * 20 + kp] = hi;
            uAl[m * 20 + kp] = lo;
        }
#pragma unroll
        for (int i = 0; i < 8; i++) {
            int idx = tid + i * 256;
            int kp = idx >> 7, n = idx & 127;
            uint32_t hi, lo;
            split2(rBx[i], rBy[i], hi, lo);
            uBh[n * 20 + kp] = hi;
            uBl[n * 20 + kp] = lo;
        }
    }

    for (int c = 0; c < 4; c++) {
        __syncthreads();                       // buffer c&1 fully staged
        if (c < 3) {
            int k0n = (c + 1) * 32;
#pragma unroll
            for (int i = 0; i < 8; i++) {
                int idx = tid + i * 256;
                int m = idx >> 4, kp = idx & 15;
                rA[i] = *(const float2*)(g_a2 + (size_t)(m0 + m) * F2 + k0n + 2 * kp);
            }
#pragma unroll
            for (int i = 0; i < 8; i++) {
                int idx = tid + i * 256;
                int kp = idx >> 7, n = idx & 127;
                rBx[i] = W2[(size_t)(k0n + 2 * kp) * F3 + n0 + n];
                rBy[i] = W2[(size_t)(k0n + 2 * kp + 1) * F3 + n0 + n];
            }
        }
        const uint32_t* cb = smu + (c & 1) * G2_BUFU;
        const uint32_t* uAh = cb;
        const uint32_t* uAl = cb + 2560;
        const uint32_t* uBh = cb + 5120;
        const uint32_t* uBl = cb + 7680;
#pragma unroll
        for (int ks = 0; ks < 2; ks++) {
            int kb = ks * 8;
#pragma unroll
            for (int mt = 0; mt < 4; mt++) {
                int r = wm * 64 + mt * 16 + gid;
                uint32_t ah[4], al[4];
                ah[0] = uAh[r * 20 + kb + tig];
                ah[1] = uAh[(r + 8) * 20 + kb + tig];
                ah[2] = uAh[r * 20 + kb + tig + 4];
                ah[3] = uAh[(r + 8) * 20 + kb + tig + 4];
                al[0] = uAl[r * 20 + kb + tig];
                al[1] = uAl[(r + 8) * 20 + kb + tig];
                al[2] = uAl[r * 20 + kb + tig + 4];
                al[3] = uAl[(r + 8) * 20 + kb + tig + 4];
#pragma unroll
                for (int nt = 0; nt < 4; nt++) {
                    int ncol = wn * 32 + nt * 8 + gid;
                    uint32_t bh0 = uBh[ncol * 20 + kb + tig];
                    uint32_t bh1 = uBh[ncol * 20 + kb + tig + 4];
                    uint32_t bl0 = uBl[ncol * 20 + kb + tig];
                    uint32_t bl1 = uBl[ncol * 20 + kb + tig + 4];
                    mma_bf16(acc[mt][nt], ah, bh0, bh1);
                    mma_bf16(acc[mt][nt], al, bh0, bh1);
                    mma_bf16(acc[mt][nt], ah, bl0, bl1);
                }
            }
        }
        if (c < 3) {
            uint32_t* nb = smu + ((c + 1) & 1) * G2_BUFU;
            uint32_t* nAh = nb;
            uint32_t* nAl = nb + 2560;
            uint32_t* nBh = nb + 5120;
            uint32_t* nBl = nb + 7680;
#pragma unroll
            for (int i = 0; i < 8; i++) {
                int idx = tid + i * 256;
                int m = idx >> 4, kp = idx & 15;
                uint32_t hi, lo;
                split2(rA[i].x, rA[i].y, hi, lo);
                nAh[m * 20 + kp] = hi;
                nAl[m * 20 + kp] = lo;
            }
#pragma unroll
            for (int i = 0; i < 8; i++) {
                int idx = tid + i * 256;
                int kp = idx >> 7, n = idx & 127;
                uint32_t hi, lo;
                split2(rBx[i], rBy[i], hi, lo);
                nBh[n * 20 + kp] = hi;
                nBl[n * 20 + kp] = lo;
            }
        }
    }

    // epilogue: bias + relu + store
#pragma unroll
    for (int mt = 0; mt < 4; mt++) {
        int r = m0 + wm * 64 + mt * 16 + gid;
#pragma unroll
        for (int nt = 0; nt < 4; nt++) {
            int ccol = n0 + wn * 32 + nt * 8 + tig * 2;
            float bb0 = __ldg(b2 + ccol), bb1 = __ldg(b2 + ccol + 1);
            float2 v0 = make_float2(fmaxf(acc[mt][nt][0] + bb0, 0.f),
                                    fmaxf(acc[mt][nt][1] + bb1, 0.f));
            float2 v1 = make_float2(fmaxf(acc[mt][nt][2] + bb0, 0.f),
                                    fmaxf(acc[mt][nt][3] + bb1, 0.f));
            *(float2*)(g_h2 + (size_t)r * F3 + ccol) = v0;
            *(float2*)(g_h2 + (size_t)(r + 8) * F3 + ccol) = v1;
        }
    }
}

// ---------------- K8: head, bf16 split mma, full-chunk W prefetch (r14) ----------------
#define H_BUFU 2304    // u32 per staging buffer (uAh[32][36] + uAl[32][36])
#define H_SMEM 40960   // dump region 8*1280*4 dominates

__global__ __launch_bounds__(256, 2) void head_mma_kernel(const float* __restrict__ v1W,
                                                          const float* __restrict__ advW) {
    extern __shared__ uint32_t smu[];
    float* smf = (float*)smu;

    int tid = threadIdx.x;
    int wid = tid >> 5, lane = tid & 31;
    int gid = lane >> 2, tig = lane & 3;
    int s = wid >> 1, h = wid & 1;
    int kb = s * 8;
    int kslice = blockIdx.x * 2048;

    float acc[2][5][4];
#pragma unroll
    for (int i = 0; i < 2; i++)
#pragma unroll
        for (int j = 0; j < 5; j++)
#pragma unroll
            for (int r = 0; r < 4; r++) acc[i][j][r] = 0.f;

    // feat prefetch chunk 0 + stage into buffer 0
    float2 rF[4];
#pragma unroll
    for (int i = 0; i < 4; i++) {
        int idx = tid + i * 256;
        int b = idx >> 5, kp = idx & 31;
        rF[i] = *(const float2*)(g_h2 + (size_t)b * KHEAD + kslice + 2 * kp);
    }
    {
        uint32_t* uAh = smu;
        uint32_t* uAl = smu + 1152;
#pragma unroll
        for (int i = 0; i < 4; i++) {
            int idx = tid + i * 256;
            int b = idx >> 5, kp = idx & 31;
            uint32_t hi, lo;
            split2(rF[i].x, rF[i].y, hi, lo);
            uAh[b * 36 + kp] = hi;
            uAl[b * 36 + kp] = lo;
        }
    }

    for (int ch = 0; ch < 32; ch++) {
        int k0 = kslice + ch * 64;
        int kgp = (k0 >> 1) + kb + tig;      // this thread's first global k-pair
        int r0 = 2 * kgp;
        // load ALL chunk weights upfront (20 scalars, MLP=20) before the barrier
        float w[5][4];
#pragma unroll
        for (int nt = 0; nt < 5; nt++)
            load_w4(w[nt], v1W, advW, r0, h * 40 + nt * 8 + gid);
        __syncthreads();                      // buffer ch&1 fully staged
        // feat prefetch next chunk
        if (ch < 31) {
#pragma unroll
            for (int i = 0; i < 4; i++) {
                int idx = tid + i * 256;
                int b = idx >> 5, kp = idx & 31;
                rF[i] = *(const float2*)(g_h2 + (size_t)b * KHEAD + k0 + 64 + 2 * kp);
            }
        }
        // A fragments from current buffer
        const uint32_t* cb = smu + (ch & 1) * H_BUFU;
        const uint32_t* uAh = cb;
        const uint32_t* uAl = cb + 1152;
        uint32_t ah[2][4], al[2][4];
#pragma unroll
        for (int mt = 0; mt < 2; mt++) {
            int b = mt * 16 + gid;
            ah[mt][0] = uAh[b * 36 + kb + tig];
            ah[mt][1] = uAh[(b + 8) * 36 + kb + tig];
            ah[mt][2] = uAh[b * 36 + kb + tig + 4];
            ah[mt][3] = uAh[(b + 8) * 36 + kb + tig + 4];
            al[mt][0] = uAl[b * 36 + kb + tig];
            al[mt][1] = uAl[(b + 8) * 36 + kb + tig];
            al[mt][2] = uAl[b * 36 + kb + tig + 4];
            al[mt][3] = uAl[(b + 8) * 36 + kb + tig + 4];
        }
        // mma over the 5 n-tiles, consuming pre-loaded weights
#pragma unroll
        for (int nt = 0; nt < 5; nt++) {
            uint32_t bh0, bl0, bh1, bl1;
            split2(w[nt][0], w[nt][1], bh0, bl0);
            split2(w[nt][2], w[nt][3], bh1, bl1);
#pragma unroll
            for (int mt = 0; mt < 2; mt++) {
                mma_bf16(acc[mt][nt], ah[mt], bh0, bh1);
                mma_bf16(acc[mt][nt], al[mt], bh0, bh1);
                mma_bf16(acc[mt][nt], ah[mt], bl0, bl1);
            }
        }
        // stage chunk ch+1 into the OTHER buffer (next loop-top sync orders it)
        if (ch < 31) {
            uint32_t* nb = smu + ((ch + 1) & 1) * H_BUFU;
            uint32_t* nAh = nb;
            uint32_t* nAl = nb + 1152;
#pragma unroll
            for (int i = 0; i < 4; i++) {
                int idx = tid + i * 256;
                int b = idx >> 5, kp = idx & 31;
                uint32_t hi, lo;
                split2(rF[i].x, rF[i].y, hi, lo);
                nAh[b * 36 + kp] = hi;
                nAl[b * 36 + kp] = lo;
            }
        }
    }

    // ---- reduction: per-warp dump (reusing smem), tree-sum, coalesced STG ----
    __syncthreads();     // all warps done reading staging buffers
    float* dump = smf + wid * 1280;
#pragma unroll
    for (int mt = 0; mt < 2; mt++) {
        int b = mt * 16 + gid;
#pragma unroll
        for (int nt = 0; nt < 5; nt++) {
            int j = nt * 8 + tig * 2;
            dump[b * 40 + j]           = acc[mt][nt][0];
            dump[b * 40 + j + 1]       = acc[mt][nt][1];
            dump[(b + 8) * 40 + j]     = acc[mt][nt][2];
            dump[(b + 8) * 40 + j + 1] = acc[mt][nt][3];
        }
    }
    __syncthreads();
    for (int i = tid; i < 2560; i += 256) {
        int b = i / 80, j = i - b * 80;
        int hh = (j >= 40) ? 1 : 0;
        int jl = j - hh * 40;
        int base = b * 40 + jl;
        float v = smf[(0 + hh) * 1280 + base] + smf[(2 + hh) * 1280 + base]
                + smf[(4 + hh) * 1280 + base] + smf[(6 + hh) * 1280 + base];
        g_Ppart[blockIdx.x][i] = v;
    }
}

// ---------------- K8b: fold partials into g_P ----------------
__global__ __launch_bounds__(256) void reduceP_kernel() {
    int i = blockIdx.x * 256 + threadIdx.x;   // 10 blocks x 256 = 2560
    if (i >= NB * 80) return;
    float s0 = 0.f, s1 = 0.f, s2 = 0.f, s3 = 0.f;
#pragma unroll 4
    for (int b = 0; b < HGB; b += 4) {
        s0 += g_Ppart[b][i];
        s1 += g_Ppart[b + 1][i];
        s2 += g_Ppart[b + 2][i];
        s3 += g_Ppart[b + 3][i];
    }
    g_P[i] = (s0 + s1) + (s2 + s3);
}

// ---------------- K9: finish heads ----------------
__global__ __launch_bounds__(256) void final_kernel(const float* __restrict__ advb, const float* __restrict__ v1b,
                             const float* __restrict__ v2W, const float* __restrict__ v2b,
                             const float* __restrict__ v3W, const float* __restrict__ v3b,
                             float* __restrict__ out) {
    __shared__ float sW[64 * 64];
    int tid = threadIdx.x;
    for (int id = tid; id < 64 * 64; id += 256) sW[id] = v2W[id];
    __syncthreads();
    int b = tid;
    if (b >= NB) return;
    float v1[64];
#pragma unroll
    for (int j = 0; j < 64; j++) v1[j] = fmaxf(g_P[b * 80 + j] + v1b[j], 0.f);
    float adv[12];
#pragma unroll
    for (int j = 0; j < 12; j++) adv[j] = fmaxf(g_P[b * 80 + 64 + j] + advb[j], 0.f);
    float val = v3b[0];
    for (int i = 0; i < 64; i++) {
        float a0 = 0.f, a1 = 0.f, a2 = 0.f, a3 = 0.f;
#pragma unroll
        for (int j = 0; j < 64; j += 4) {
            a0 = fmaf(v1[j],     sW[(j)     * 64 + i], a0);
            a1 = fmaf(v1[j + 1], sW[(j + 1) * 64 + i], a1);
            a2 = fmaf(v1[j + 2], sW[(j + 2) * 64 + i], a2);
            a3 = fmaf(v1[j + 3], sW[(j + 3) * 64 + i], a3);
        }
        float a = (a0 + a1) + (a2 + a3) + v2b[i];
        val = fmaf(fmaxf(a, 0.f), v3W[i], val);
    }
#pragma unroll
    for (int h = 0; h < 3; h++) {
        float m = 0.25f * (adv[4 * h] + adv[4 * h + 1] + adv[4 * h + 2] + adv[4 * h + 3]);
#pragma unroll
        for (int a = 0; a < 4; a++)
            out[b * 12 + h * 4 + a] = val + adv[4 * h + a] - m;
    }
}

// ---------------- launch ----------------
extern "C" void kernel_launch(void* const* d_in, const int* in_sizes, int n_in,
                              void* d_out, int out_size) {
    const float* x    = (const float*)d_in[0];
    const void*  ei   = d_in[1];
    const float* ew   = (const float*)d_in[2];
    const float* W1   = (const float*)d_in[3];
    const float* b1   = (const float*)d_in[4];
    const float* W2   = (const float*)d_in[5];
    const float* b2   = (const float*)d_in[6];
    const float* advW = (const float*)d_in[7];
    const float* advb = (const float*)d_in[8];
    const float* v1W  = (const float*)d_in[9];
    const float* v1b  = (const float*)d_in[10];
    const float* v2W  = (const float*)d_in[11];
    const float* v2b  = (const float*)d_in[12];
    const float* v3W  = (const float*)d_in[13];
    const float* v3b  = (const float*)d_in[14];
    float* out = (float*)d_out;

    static int attr_done = 0;
    if (!attr_done) {
        cudaFuncSetAttribute(gemm2_mma_kernel, cudaFuncAttributeMaxDynamicSharedMemorySize, G2_SMEM);
        attr_done = 1;
    }

    zero_kernel<<<16, 256>>>((const int*)ei);
    degcnt_kernel<<<NEDGE / 256, 256>>>(ei, ew);
    scan_kernel<<<1, 1024>>>();
    fill_kernel<<<NEDGE / 256, 256>>>(ei, ew);
    agg16_gemm1_kernel<<<NNODE, 512>>>(x, W1, b1);
    agg128_kernel<<<NNODE, 512>>>();
    gemm2_mma_kernel<<<dim3(2, NROWS / 128), 256, G2_SMEM>>>(W2, b2);
    head_mma_kernel<<<HGB, 256, H_SMEM>>>(v1W, advW);
    reduceP_kernel<<<10, 256>>>();
    final_kernel<<<1, 256>>>(advb, v1b, v2W, v2b, v3W, v3b, out);
}

// round 17
// speedup vs baseline: 1.0591x; 1.0591x over previous
#include <cuda_runtime.h>
#include <cuda_bf16.h>
#include <cstdint>

// ---------------- problem constants ----------------
#define NB      32
#define NNODE   4096
#define NEDGE   16384
#define F1      16
#define F2      128
#define F3      256
#define KHEAD   (NNODE * F3)   // 1,048,576
#define NROWS   (NB * NNODE)   // 131072

// ---------------- scratch ----------------
__device__ float g_a1[(size_t)NB * NNODE * F1];
__device__ float g_h1[(size_t)NB * NNODE * F2];
__device__ float g_a2[(size_t)NB * NNODE * F2];
__device__ float g_h2[(size_t)NB * NNODE * F3];
__device__ float g_deg[NNODE];
__device__ float g_dinv[NNODE];
__device__ int   g_cnt[NNODE];
__device__ int   g_fill[NNODE];
__device__ int   g_rowptr[NNODE + 1];
__device__ int   g_col[NEDGE];
__device__ float g_nrm[NEDGE];
__device__ float g_P[NB * 80];
__device__ int   g_is64;

#define HGB 512
__device__ float g_Ppart[HGB][NB * 80];   // 5.24 MB per-block head partials

// ---------------- helpers ----------------
// truncation-based split of a float pair into bf16x2 hi/lo words.
__device__ __forceinline__ void split2(float x, float y, uint32_t& hi, uint32_t& lo) {
    uint32_t xb = __float_as_uint(x), yb = __float_as_uint(y);
    hi = __byte_perm(xb, yb, 0x7632);
    float lx = x - __uint_as_float(xb & 0xffff0000u);
    float ly = y - __uint_as_float(yb & 0xffff0000u);
    lo = __byte_perm(__float_as_uint(lx), __float_as_uint(ly), 0x7632);
}
// D += A(16x16 bf16) * B(16x8 bf16), f32 accum. m16n8k16 fragments.
__device__ __forceinline__ void mma_bf16(float* d, const uint32_t* a, uint32_t b0, uint32_t b1) {
    asm volatile(
        "mma.sync.aligned.m16n8k16.row.col.f32.bf16.bf16.f32 "
        "{%0,%1,%2,%3}, {%4,%5,%6,%7}, {%8,%9}, {%0,%1,%2,%3};"
        : "+f"(d[0]), "+f"(d[1]), "+f"(d[2]), "+f"(d[3])
        : "r"(a[0]), "r"(a[1]), "r"(a[2]), "r"(a[3]), "r"(b0), "r"(b1));
}
// head weight fragment load: rows r0, r0+1, r0+8, r0+9 at output-col ncol of [v1W|advW|0]
__device__ __forceinline__ void load_w4(float* dst, const float* __restrict__ v1W,
                                        const float* __restrict__ advW, int r0, int ncol) {
    if (ncol < 64) {
        const float* p = v1W + (size_t)r0 * 64 + ncol;
        dst[0] = p[0]; dst[1] = p[64]; dst[2] = p[512]; dst[3] = p[576];
    } else if (ncol < 76) {
        const float* p = advW + (size_t)r0 * 12 + (ncol - 64);
        dst[0] = p[0]; dst[1] = p[12]; dst[2] = p[96]; dst[3] = p[108];
    } else {
        dst[0] = dst[1] = dst[2] = dst[3] = 0.f;
    }
}

// ---------------- edge read helper ----------------
__device__ __forceinline__ void read_edge(const void* ei, int e, int& src, int& dst) {
    if (g_is64) {
        const long long* p = (const long long*)ei;
        src = (int)p[e]; dst = (int)p[NEDGE + e];
    } else {
        const int* p = (const int*)ei;
        src = p[e]; dst = p[NEDGE + e];
    }
}

// ---------------- K0 ----------------
__global__ void zero_kernel(const int* __restrict__ ei32) {
    int i = blockIdx.x * blockDim.x + threadIdx.x;
    if (i < NNODE) { g_deg[i] = 0.f; g_cnt[i] = 0; g_fill[i] = 0; }
    if (i == 0) {
        int any = 0;
        for (int k = 0; k < 256; k++) any |= ei32[2 * k + 1];
        g_is64 = (any == 0) ? 1 : 0;
    }
}

// ---------------- K1 ----------------
__global__ void degcnt_kernel(const void* __restrict__ ei, const float* __restrict__ ew) {
    int e = blockIdx.x * blockDim.x + threadIdx.x;
    if (e >= NEDGE) return;
    int src, dst;
    read_edge(ei, e, src, dst);
    atomicAdd(&g_deg[dst], ew[e]);
    atomicAdd(&g_cnt[dst], 1);
}

// ---------------- K2 ----------------
__global__ __launch_bounds__(1024) void scan_kernel() {
    __shared__ int ss[1024];
    int t = threadIdx.x;
    int loc[4]; int s = 0;
#pragma unroll
    for (int i = 0; i < 4; i++) { loc[i] = s; s += g_cnt[4 * t + i]; }
    ss[t] = s;
    __syncthreads();
    int mysum = s;
    for (int off = 1; off < 1024; off <<= 1) {
        int v = (t >= off) ? ss[t - off] : 0;
        __syncthreads();
        ss[t] += v;
        __syncthreads();
    }
    int excl = ss[t] - mysum;
#pragma unroll
    for (int i = 0; i < 4; i++) {
        g_rowptr[4 * t + i] = excl + loc[i];
        g_dinv[4 * t + i] = rsqrtf(g_deg[4 * t + i] + 1.0f);
    }
    if (t == 1023) g_rowptr[NNODE] = ss[t];
}

// ---------------- K3 ----------------
__global__ void fill_kernel(const void* __restrict__ ei, const float* __restrict__ ew) {
    int e = blockIdx.x * blockDim.x + threadIdx.x;
    if (e >= NEDGE) return;
    int src, dst;
    read_edge(ei, e, src, dst);
    int pos = g_rowptr[dst] + atomicAdd(&g_fill[dst], 1);
    g_col[pos] = src;
    g_nrm[pos] = ew[e] * g_dinv[src] * g_dinv[dst];
}

// ---------------- K4: aggregate x (F=16) ----------------
__global__ __launch_bounds__(512) void agg16_kernel(const float* __restrict__ x) {
    int n = blockIdx.x;
    int tid = threadIdx.x;
    int b = tid >> 4, f = tid & 15;
    int beg = g_rowptr[n], end = g_rowptr[n + 1];
    float d = g_dinv[n];
    float d2 = d * d;
    const float* xb = x + (size_t)b * (NNODE * F1);
    float acc = d2 * xb[n * F1 + f];
    for (int j = beg; j < end; j++)
        acc = fmaf(g_nrm[j], xb[(size_t)g_col[j] * F1 + f], acc);
    g_a1[((size_t)b * NNODE + n) * F1 + f] = acc;
}

// ---------------- K5: gemm1 ----------------
__global__ __launch_bounds__(256) void gemm1_kernel(const float* __restrict__ W1, const float* __restrict__ b1) {
    __shared__ float Ws[16][128];
    __shared__ float bs[128];
    int tid = threadIdx.x;
    for (int id = tid; id < 16 * 128; id += 256) Ws[id >> 7][id & 127] = W1[id];
    if (tid < 128) bs[tid] = b1[tid];
    __syncthreads();
    int wid = tid >> 5, lane = tid & 31;
    size_t row = (size_t)blockIdx.x * 8 + wid;
    float av = (lane < 16) ? g_a1[row * F1 + lane] : 0.f;
    float acc[4] = {0.f, 0.f, 0.f, 0.f};
#pragma unroll
    for (int k = 0; k < 16; k++) {
        float a = __shfl_sync(0xffffffffu, av, k);
#pragma unroll
        for (int c = 0; c < 4; c++) acc[c] = fmaf(a, Ws[k][lane + 32 * c], acc[c]);
    }
#pragma unroll
    for (int c = 0; c < 4; c++)
        g_h1[row * F2 + lane + 32 * c] = fmaxf(acc[c] + bs[lane + 32 * c], 0.f);
}

// ---------------- K6: aggregate h1 (F=128), depth-1 pipelined gather ----------------
__global__ __launch_bounds__(512) void agg128_kernel() {
    int n = blockIdx.x;
    int tid = threadIdx.x;
    int b = tid >> 4, q = tid & 15;
    int beg = g_rowptr[n], end = g_rowptr[n + 1];
    float d = g_dinv[n];
    float d2 = d * d;
    const float4* hb = (const float4*)g_h1 + (size_t)b * (NNODE * 32);
    float4 s0 = hb[(size_t)n * 32 + q];
    float4 s1 = hb[(size_t)n * 32 + 16 + q];
    float4 a0 = make_float4(d2 * s0.x, d2 * s0.y, d2 * s0.z, d2 * s0.w);
    float4 a1 = make_float4(d2 * s1.x, d2 * s1.y, d2 * s1.z, d2 * s1.w);
    if (beg < end) {
        float w = g_nrm[beg];
        size_t c = (size_t)g_col[beg] * 32;
        float4 v0 = hb[c + q];
        float4 v1 = hb[c + 16 + q];
        for (int j = beg + 1; j < end; j++) {
            float wn = g_nrm[j];
            size_t cn = (size_t)g_col[j] * 32;
            float4 u0 = hb[cn + q];
            float4 u1 = hb[cn + 16 + q];
            a0.x = fmaf(w, v0.x, a0.x); a0.y = fmaf(w, v0.y, a0.y);
            a0.z = fmaf(w, v0.z, a0.z); a0.w = fmaf(w, v0.w, a0.w);
            a1.x = fmaf(w, v1.x, a1.x); a1.y = fmaf(w, v1.y, a1.y);
            a1.z = fmaf(w, v1.z, a1.z); a1.w = fmaf(w, v1.w, a1.w);
            w = wn; v0 = u0; v1 = u1;
        }
        a0.x = fmaf(w, v0.x, a0.x); a0.y = fmaf(w, v0.y, a0.y);
        a0.z = fmaf(w, v0.z, a0.z); a0.w = fmaf(w, v0.w, a0.w);
        a1.x = fmaf(w, v1.x, a1.x); a1.y = fmaf(w, v1.y, a1.y);
        a1.z = fmaf(w, v1.z, a1.z); a1.w = fmaf(w, v1.w, a1.w);
    }
    float4* ob = (float4*)g_a2 + (size_t)b * (NNODE * 32);
    ob[(size_t)n * 32 + q] = a0;
    ob[(size_t)n * 32 + 16 + q] = a1;
}

// ---------------- K7: gemm2, bf16 split mma, double-buffered smem ----------------
#define G2_BUFU 10240    // u32 per buffer
#define G2_SMEM 81920

__global__ __launch_bounds__(256, 2) void gemm2_mma_kernel(const float* __restrict__ W2,
                                                           const float* __restrict__ b2) {
    extern __shared__ uint32_t smu[];

    int tid = threadIdx.x;
    int wid = tid >> 5, lane = tid & 31;
    int gid = lane >> 2, tig = lane & 3;
    int wm = wid & 1, wn = wid >> 1;
    int m0 = blockIdx.y * 128;
    int n0 = blockIdx.x * 128;

    float acc[4][4][4];
#pragma unroll
    for (int i = 0; i < 4; i++)
#pragma unroll
        for (int j = 0; j < 4; j++)
#pragma unroll
            for (int r = 0; r < 4; r++) acc[i][j][r] = 0.f;

    float2 rA[8];
    float  rBx[8], rBy[8];
    // prefetch chunk 0
#pragma unroll
    for (int i = 0; i < 8; i++) {
        int idx = tid + i * 256;
        int m = idx >> 4, kp = idx & 15;
        rA[i] = *(const float2*)(g_a2 + (size_t)(m0 + m) * F2 + 2 * kp);
    }
#pragma unroll
    for (int i = 0; i < 8; i++) {
        int idx = tid + i * 256;
        int kp = idx >> 7, n = idx & 127;
        rBx[i] = W2[(size_t)(2 * kp) * F3 + n0 + n];
        rBy[i] = W2[(size_t)(2 * kp + 1) * F3 + n0 + n];
    }
    // stage chunk 0 into buffer 0
    {
        uint32_t* uAh = smu;
        uint32_t* uAl = smu + 2560;
        uint32_t* uBh = smu + 5120;
        uint32_t* uBl = smu + 7680;
#pragma unroll
        for (int i = 0; i < 8; i++) {
            int idx = tid + i * 256;
            int m = idx >> 4, kp = idx & 15;
            uint32_t hi, lo;
            split2(rA[i].x, rA[i].y, hi, lo);
            uAh[m * 20 + kp] = hi;
            uAl[m * 20 + kp] = lo;
        }
#pragma unroll
        for (int i = 0; i < 8; i++) {
            int idx = tid + i * 256;
            int kp = idx >> 7, n = idx & 127;
            uint32_t hi, lo;
            split2(rBx[i], rBy[i], hi, lo);
            uBh[n * 20 + kp] = hi;
            uBl[n * 20 + kp] = lo;
        }
    }

    for (int c = 0; c < 4; c++) {
        __syncthreads();                       // buffer c&1 fully staged
        if (c < 3) {
            int k0n = (c + 1) * 32;
#pragma unroll
            for (int i = 0; i < 8; i++) {
                int idx = tid + i * 256;
                int m = idx >> 4, kp = idx & 15;
                rA[i] = *(const float2*)(g_a2 + (size_t)(m0 + m) * F2 + k0n + 2 * kp);
            }
#pragma unroll
            for (int i = 0; i < 8; i++) {
                int idx = tid + i * 256;
                int kp = idx >> 7, n = idx & 127;
                rBx[i] = W2[(size_t)(k0n + 2 * kp) * F3 + n0 + n];
                rBy[i] = W2[(size_t)(k0n + 2 * kp + 1) * F3 + n0 + n];
            }
        }
        const uint32_t* cb = smu + (c & 1) * G2_BUFU;
        const uint32_t* uAh = cb;
        const uint32_t* uAl = cb + 2560;
        const uint32_t* uBh = cb + 5120;
        const uint32_t* uBl = cb + 7680;
#pragma unroll
        for (int ks = 0; ks < 2; ks++) {
            int kb = ks * 8;
#pragma unroll
            for (int mt = 0; mt < 4; mt++) {
                int r = wm * 64 + mt * 16 + gid;
                uint32_t ah[4], al[4];
                ah[0] = uAh[r * 20 + kb + tig];
                ah[1] = uAh[(r + 8) * 20 + kb + tig];
                ah[2] = uAh[r * 20 + kb + tig + 4];
                ah[3] = uAh[(r + 8) * 20 + kb + tig + 4];
                al[0] = uAl[r * 20 + kb + tig];
                al[1] = uAl[(r + 8) * 20 + kb + tig];
                al[2] = uAl[r * 20 + kb + tig + 4];
                al[3] = uAl[(r + 8) * 20 + kb + tig + 4];
#pragma unroll
                for (int nt = 0; nt < 4; nt++) {
                    int ncol = wn * 32 + nt * 8 + gid;
                    uint32_t bh0 = uBh[ncol * 20 + kb + tig];
                    uint32_t bh1 = uBh[ncol * 20 + kb + tig + 4];
                    uint32_t bl0 = uBl[ncol * 20 + kb + tig];
                    uint32_t bl1 = uBl[ncol * 20 + kb + tig + 4];
                    mma_bf16(acc[mt][nt], ah, bh0, bh1);
                    mma_bf16(acc[mt][nt], al, bh0, bh1);
                    mma_bf16(acc[mt][nt], ah, bl0, bl1);
                }
            }
        }
        if (c < 3) {
            uint32_t* nb = smu + ((c + 1) & 1) * G2_BUFU;
            uint32_t* nAh = nb;
            uint32_t* nAl = nb + 2560;
            uint32_t* nBh = nb + 5120;
            uint32_t* nBl = nb + 7680;
#pragma unroll
            for (int i = 0; i < 8; i++) {
                int idx = tid + i * 256;
                int m = idx >> 4, kp = idx & 15;
                uint32_t hi, lo;
                split2(rA[i].x, rA[i].y, hi, lo);
                nAh[m * 20 + kp] = hi;
                nAl[m * 20 + kp] = lo;
            }
#pragma unroll
            for (int i = 0; i < 8; i++) {
                int idx = tid + i * 256;
                int kp = idx >> 7, n = idx & 127;
                uint32_t hi, lo;
                split2(rBx[i], rBy[i], hi, lo);
                nBh[n * 20 + kp] = hi;
                nBl[n * 20 + kp] = lo;
            }
        }
    }

    // epilogue: bias + relu + store
#pragma unroll
    for (int mt = 0; mt < 4; mt++) {
        int r = m0 + wm * 64 + mt * 16 + gid;
#pragma unroll
        for (int nt = 0; nt < 4; nt++) {
            int ccol = n0 + wn * 32 + nt * 8 + tig * 2;
            float bb0 = __ldg(b2 + ccol), bb1 = __ldg(b2 + ccol + 1);
            float2 v0 = make_float2(fmaxf(acc[mt][nt][0] + bb0, 0.f),
                                    fmaxf(acc[mt][nt][1] + bb1, 0.f));
            float2 v1 = make_float2(fmaxf(acc[mt][nt][2] + bb0, 0.f),
                                    fmaxf(acc[mt][nt][3] + bb1, 0.f));
            *(float2*)(g_h2 + (size_t)r * F3 + ccol) = v0;
            *(float2*)(g_h2 + (size_t)(r + 8) * F3 + ccol) = v1;
        }
    }
}

// ---------------- K8: head, bf16 split mma, full-chunk W prefetch (r14) ----------------
#define H_BUFU 2304    // u32 per staging buffer (uAh[32][36] + uAl[32][36])
#define H_SMEM 40960   // dump region 8*1280*4 dominates

__global__ __launch_bounds__(256, 2) void head_mma_kernel(const float* __restrict__ v1W,
                                                          const float* __restrict__ advW) {
    extern __shared__ uint32_t smu[];
    float* smf = (float*)smu;

    int tid = threadIdx.x;
    int wid = tid >> 5, lane = tid & 31;
    int gid = lane >> 2, tig = lane & 3;
    int s = wid >> 1, h = wid & 1;
    int kb = s * 8;
    int kslice = blockIdx.x * 2048;

    float acc[2][5][4];
#pragma unroll
    for (int i = 0; i < 2; i++)
#pragma unroll
        for (int j = 0; j < 5; j++)
#pragma unroll
            for (int r = 0; r < 4; r++) acc[i][j][r] = 0.f;

    // feat prefetch chunk 0 + stage into buffer 0
    float2 rF[4];
#pragma unroll
    for (int i = 0; i < 4; i++) {
        int idx = tid + i * 256;
        int b = idx >> 5, kp = idx & 31;
        rF[i] = *(const float2*)(g_h2 + (size_t)b * KHEAD + kslice + 2 * kp);
    }
    {
        uint32_t* uAh = smu;
        uint32_t* uAl = smu + 1152;
#pragma unroll
        for (int i = 0; i < 4; i++) {
            int idx = tid + i * 256;
            int b = idx >> 5, kp = idx & 31;
            uint32_t hi, lo;
            split2(rF[i].x, rF[i].y, hi, lo);
            uAh[b * 36 + kp] = hi;
            uAl[b * 36 + kp] = lo;
        }
    }

    for (int ch = 0; ch < 32; ch++) {
        int k0 = kslice + ch * 64;
        int kgp = (k0 >> 1) + kb + tig;      // this thread's first global k-pair
        int r0 = 2 * kgp;
        // load ALL chunk weights upfront (20 scalars, MLP=20) before the barrier
        float w[5][4];
#pragma unroll
        for (int nt = 0; nt < 5; nt++)
            load_w4(w[nt], v1W, advW, r0, h * 40 + nt * 8 + gid);
        __syncthreads();                      // buffer ch&1 fully staged
        // feat prefetch next chunk
        if (ch < 31) {
#pragma unroll
            for (int i = 0; i < 4; i++) {
                int idx = tid + i * 256;
                int b = idx >> 5, kp = idx & 31;
                rF[i] = *(const float2*)(g_h2 + (size_t)b * KHEAD + k0 + 64 + 2 * kp);
            }
        }
        // A fragments from current buffer
        const uint32_t* cb = smu + (ch & 1) * H_BUFU;
        const uint32_t* uAh = cb;
        const uint32_t* uAl = cb + 1152;
        uint32_t ah[2][4], al[2][4];
#pragma unroll
        for (int mt = 0; mt < 2; mt++) {
            int b = mt * 16 + gid;
            ah[mt][0] = uAh[b * 36 + kb + tig];
            ah[mt][1] = uAh[(b + 8) * 36 + kb + tig];
            ah[mt][2] = uAh[b * 36 + kb + tig + 4];
            ah[mt][3] = uAh[(b + 8) * 36 + kb + tig + 4];
            al[mt][0] = uAl[b * 36 + kb + tig];
            al[mt][1] = uAl[(b + 8) * 36 + kb + tig];
            al[mt][2] = uAl[b * 36 + kb + tig + 4];
            al[mt][3] = uAl[(b + 8) * 36 + kb + tig + 4];
        }
        // mma over the 5 n-tiles, consuming pre-loaded weights
#pragma unroll
        for (int nt = 0; nt < 5; nt++) {
            uint32_t bh0, bl0, bh1, bl1;
            split2(w[nt][0], w[nt][1], bh0, bl0);
            split2(w[nt][2], w[nt][3], bh1, bl1);
#pragma unroll
            for (int mt = 0; mt < 2; mt++) {
                mma_bf16(acc[mt][nt], ah[mt], bh0, bh1);
                mma_bf16(acc[mt][nt], al[mt], bh0, bh1);
                mma_bf16(acc[mt][nt], ah[mt], bl0, bl1);
            }
        }
        // stage chunk ch+1 into the OTHER buffer (next loop-top sync orders it)
        if (ch < 31) {
            uint32_t* nb = smu + ((ch + 1) & 1) * H_BUFU;
            uint32_t* nAh = nb;
            uint32_t* nAl = nb + 1152;
#pragma unroll
            for (int i = 0; i < 4; i++) {
                int idx = tid + i * 256;
                int b = idx >> 5, kp = idx & 31;
                uint32_t hi, lo;
                split2(rF[i].x, rF[i].y, hi, lo);
                nAh[b * 36 + kp] = hi;
                nAl[b * 36 + kp] = lo;
            }
        }
    }

    // ---- reduction: per-warp dump (reusing smem), tree-sum, coalesced STG ----
    __syncthreads();     // all warps done reading staging buffers
    float* dump = smf + wid * 1280;
#pragma unroll
    for (int mt = 0; mt < 2; mt++) {
        int b = mt * 16 + gid;
#pragma unroll
        for (int nt = 0; nt < 5; nt++) {
            int j = nt * 8 + tig * 2;
            dump[b * 40 + j]           = acc[mt][nt][0];
            dump[b * 40 + j + 1]       = acc[mt][nt][1];
            dump[(b + 8) * 40 + j]     = acc[mt][nt][2];
            dump[(b + 8) * 40 + j + 1] = acc[mt][nt][3];
        }
    }
    __syncthreads();
    for (int i = tid; i < 2560; i += 256) {
        int b = i / 80, j = i - b * 80;
        int hh = (j >= 40) ? 1 : 0;
        int jl = j - hh * 40;
        int base = b * 40 + jl;
        float v = smf[(0 + hh) * 1280 + base] + smf[(2 + hh) * 1280 + base]
                + smf[(4 + hh) * 1280 + base] + smf[(6 + hh) * 1280 + base];
        g_Ppart[blockIdx.x][i] = v;
    }
}

// ---------------- K8b: fold partials into g_P ----------------
__global__ __launch_bounds__(256) void reduceP_kernel() {
    int i = blockIdx.x * 256 + threadIdx.x;   // 10 blocks x 256 = 2560
    if (i >= NB * 80) return;
    float s0 = 0.f, s1 = 0.f, s2 = 0.f, s3 = 0.f;
#pragma unroll 4
    for (int b = 0; b < HGB; b += 4) {
        s0 += g_Ppart[b][i];
        s1 += g_Ppart[b + 1][i];
        s2 += g_Ppart[b + 2][i];
        s3 += g_Ppart[b + 3][i];
    }
    g_P[i] = (s0 + s1) + (s2 + s3);
}

// ---------------- K9: finish heads ----------------
__global__ __launch_bounds__(256) void final_kernel(const float* __restrict__ advb, const float* __restrict__ v1b,
                             const float* __restrict__ v2W, const float* __restrict__ v2b,
                             const float* __restrict__ v3W, const float* __restrict__ v3b,
                             float* __restrict__ out) {
    __shared__ float sW[64 * 64];
    int tid = threadIdx.x;
    for (int id = tid; id < 64 * 64; id += 256) sW[id] = v2W[id];
    __syncthreads();
    int b = tid;
    if (b >= NB) return;
    float v1[64];
#pragma unroll
    for (int j = 0; j < 64; j++) v1[j] = fmaxf(g_P[b * 80 + j] + v1b[j], 0.f);
    float adv[12];
#pragma unroll
    for (int j = 0; j < 12; j++) adv[j] = fmaxf(g_P[b * 80 + 64 + j] + advb[j], 0.f);
    float val = v3b[0];
    for (int i = 0; i < 64; i++) {
        float a0 = 0.f, a1 = 0.f, a2 = 0.f, a3 = 0.f;
#pragma unroll
        for (int j = 0; j < 64; j += 4) {
            a0 = fmaf(v1[j],     sW[(j)     * 64 + i], a0);
            a1 = fmaf(v1[j + 1], sW[(j + 1) * 64 + i], a1);
            a2 = fmaf(v1[j + 2], sW[(j + 2) * 64 + i], a2);
            a3 = fmaf(v1[j + 3], sW[(j + 3) * 64 + i], a3);
        }
        float a = (a0 + a1) + (a2 + a3) + v2b[i];
        val = fmaf(fmaxf(a, 0.f), v3W[i], val);
    }
#pragma unroll
    for (int h = 0; h < 3; h++) {
        float m = 0.25f * (adv[4 * h] + adv[4 * h + 1] + adv[4 * h + 2] + adv[4 * h + 3]);
#pragma unroll
        for (int a = 0; a < 4; a++)
            out[b * 12 + h * 4 + a] = val + adv[4 * h + a] - m;
    }
}

// ---------------- launch ----------------
extern "C" void kernel_launch(void* const* d_in, const int* in_sizes, int n_in,
                              void* d_out, int out_size) {
    const float* x    = (const float*)d_in[0];
    const void*  ei   = d_in[1];
    const float* ew   = (const float*)d_in[2];
    const float* W1   = (const float*)d_in[3];
    const float* b1   = (const float*)d_in[4];
    const float* W2   = (const float*)d_in[5];
    const float* b2   = (const float*)d_in[6];
    const float* advW = (const float*)d_in[7];
    const float* advb = (const float*)d_in[8];
    const float* v1W  = (const float*)d_in[9];
    const float* v1b  = (const float*)d_in[10];
    const float* v2W  = (const float*)d_in[11];
    const float* v2b  = (const float*)d_in[12];
    const float* v3W  = (const float*)d_in[13];
    const float* v3b  = (const float*)d_in[14];
    float* out = (float*)d_out;

    static int attr_done = 0;
    if (!attr_done) {
        cudaFuncSetAttribute(gemm2_mma_kernel, cudaFuncAttributeMaxDynamicSharedMemorySize, G2_SMEM);
        attr_done = 1;
    }

    zero_kernel<<<16, 256>>>((const int*)ei);
    degcnt_kernel<<<NEDGE / 256, 256>>>(ei, ew);
    scan_kernel<<<1, 1024>>>();
    fill_kernel<<<NEDGE / 256, 256>>>(ei, ew);
    agg16_kernel<<<NNODE, 512>>>(x);
    gemm1_kernel<<<NROWS / 8, 256>>>(W1, b1);
    agg128_kernel<<<NNODE, 512>>>();
    gemm2_mma_kernel<<<dim3(2, NROWS / 128), 256, G2_SMEM>>>(W2, b2);
    head_mma_kernel<<<HGB, 256, H_SMEM>>>(v1W, advW);
    reduceP_kernel<<<10, 256>>>();
    final_kernel<<<1, 256>>>(advb, v1b, v2W, v2b, v3W, v3b, out);
}